// round 3
// baseline (speedup 1.0000x reference)
#include <cuda_runtime.h>
#include <cuda_bf16.h>
#include <cstdint>

// ---------------------------------------------------------------------------
// CopyNet pointer-generator mix, fused single kernel.
//   out[b,t,v] = p_gen[b,t] * (v < V ? dist[b,t,v] : 0)
//              + (1 - p_gen[b,t]) * sum_{s: pointer[b,s]==v} alph[b,s,t]
//
// One CTA per output row (b,t). The row's copy-distribution (scatter of
// L_SRC attention weights into V_EXT slots) is accumulated in shared memory,
// then fused with the streaming pg*dist read -> single write of the output
// row. No global atomics, no second DRAM pass.
// ---------------------------------------------------------------------------

__global__ void copynet_fused_kernel(const float* __restrict__ dist,
                                     const float* __restrict__ p_gen,
                                     const float* __restrict__ alph,
                                     const int*   __restrict__ pointer,
                                     float* __restrict__ out,
                                     int V4, int Vext4,
                                     int L_DEC, int L_SRC)
{
    extern __shared__ float srow[];            // Vext floats (copyp accumulator)
    float4* s4 = reinterpret_cast<float4*>(srow);

    int row = blockIdx.x;                      // b*L_DEC + t
    int b   = row / L_DEC;
    int t   = row - b * L_DEC;
    float pg = __ldg(&p_gen[row]);
    float one_m = 1.0f - pg;

    // Phase 1: zero the shared accumulator.
    float4 z = make_float4(0.f, 0.f, 0.f, 0.f);
    for (int i = threadIdx.x; i < Vext4; i += blockDim.x)
        s4[i] = z;
    __syncthreads();

    // Phase 2: scatter this row's L_SRC contributions into shared.
    // alph layout [B, L_SRC, L_DEC]: element (b, s, t) at b*L_SRC*L_DEC + s*L_DEC + t.
    {
        const float* arow = alph + ((size_t)b * L_SRC) * L_DEC + t;
        const int*   prow = pointer + b * L_SRC;
        for (int s = threadIdx.x; s < L_SRC; s += blockDim.x) {
            float a = __ldg(&arow[(size_t)s * L_DEC]);
            int   p = __ldg(&prow[s]);
            atomicAdd(&srow[p], one_m * a);
        }
    }
    __syncthreads();

    // Phase 3: fused stream: out = pg*dist (+ pad zeros) + copyp.
    {
        const float4* src = reinterpret_cast<const float4*>(dist) + (size_t)row * V4;
        float4*       dst = reinterpret_cast<float4*>(out)        + (size_t)row * Vext4;
        for (int i = threadIdx.x; i < Vext4; i += blockDim.x) {
            float4 c = s4[i];
            if (i < V4) {
                float4 d = __ldg(&src[i]);
                c.x = fmaf(pg, d.x, c.x);
                c.y = fmaf(pg, d.y, c.y);
                c.z = fmaf(pg, d.z, c.z);
                c.w = fmaf(pg, d.w, c.w);
            }
            dst[i] = c;
        }
    }
}

// Scalar fallback for vocab sizes not divisible by 4 (same algorithm).
__global__ void copynet_fused_scalar_kernel(const float* __restrict__ dist,
                                            const float* __restrict__ p_gen,
                                            const float* __restrict__ alph,
                                            const int*   __restrict__ pointer,
                                            float* __restrict__ out,
                                            int V, int Vext,
                                            int L_DEC, int L_SRC)
{
    extern __shared__ float srow[];
    int row = blockIdx.x;
    int b   = row / L_DEC;
    int t   = row - b * L_DEC;
    float pg = __ldg(&p_gen[row]);
    float one_m = 1.0f - pg;

    for (int i = threadIdx.x; i < Vext; i += blockDim.x)
        srow[i] = 0.f;
    __syncthreads();

    const float* arow = alph + ((size_t)b * L_SRC) * L_DEC + t;
    const int*   prow = pointer + b * L_SRC;
    for (int s = threadIdx.x; s < L_SRC; s += blockDim.x)
        atomicAdd(&srow[__ldg(&prow[s])], one_m * __ldg(&arow[(size_t)s * L_DEC]));
    __syncthreads();

    for (int i = threadIdx.x; i < Vext; i += blockDim.x) {
        float c = srow[i];
        if (i < V) c = fmaf(pg, __ldg(&dist[(size_t)row * V + i]), c);
        out[(size_t)row * Vext + i] = c;
    }
}

extern "C" void kernel_launch(void* const* d_in, const int* in_sizes, int n_in,
                              void* d_out, int out_size)
{
    // metadata order: dist_t, p_gen, alph_t, batch_vocab, pointer
    const float* dist    = (const float*)d_in[0];
    const float* p_gen   = (const float*)d_in[1];
    const float* alph    = (const float*)d_in[2];
    const int*   pointer = (const int*)d_in[4];
    float*       out     = (float*)d_out;

    int BT    = in_sizes[1];                 // B * L_DEC   (2048)
    int Vext  = in_sizes[3];                 // 32128
    int BS    = in_sizes[4];                 // B * L_SRC   (4096)
    int L_DEC = in_sizes[2] / BS;            // 256
    int B     = BT / L_DEC;                  // 8
    int L_SRC = BS / B;                      // 512
    int V     = in_sizes[0] / BT;            // 32000

    size_t smem_bytes = (size_t)Vext * sizeof(float);   // 128.5 KB
    const int TPB = 1024;

    if ((V % 4 == 0) && (Vext % 4 == 0)) {
        cudaFuncSetAttribute(copynet_fused_kernel,
                             cudaFuncAttributeMaxDynamicSharedMemorySize,
                             (int)smem_bytes);
        copynet_fused_kernel<<<BT, TPB, smem_bytes>>>(
            dist, p_gen, alph, pointer, out, V / 4, Vext / 4, L_DEC, L_SRC);
    } else {
        cudaFuncSetAttribute(copynet_fused_scalar_kernel,
                             cudaFuncAttributeMaxDynamicSharedMemorySize,
                             (int)smem_bytes);
        copynet_fused_scalar_kernel<<<BT, TPB, smem_bytes>>>(
            dist, p_gen, alph, pointer, out, V, Vext, L_DEC, L_SRC);
    }
}

// round 5
// speedup vs baseline: 1.2397x; 1.2397x over previous
#include <cuda_runtime.h>
#include <cuda_bf16.h>
#include <cstdint>

// ---------------------------------------------------------------------------
// CopyNet pointer-generator mix, fused, vocab-chunked.
//   out[b,t,v] = p_gen[b,t] * (v < V ? dist[b,t,v] : 0)
//              + (1 - p_gen[b,t]) * sum_{s: pointer[b,s]==v} alph[b,s,t]
//
// Each output row (b,t) is split into NCHUNK vocab chunks; one CTA per
// (row, chunk). The chunk's copy-distribution is accumulated in a small
// (16 KB) shared buffer -> 8 CTAs/SM, 100% occupancy, phases overlap
// across CTAs. Single fused DRAM pass, no global atomics.
// ---------------------------------------------------------------------------

#define NCHUNK 8

__global__ __launch_bounds__(256)
void copynet_fused_chunk_kernel(const float* __restrict__ dist,
                                const float* __restrict__ p_gen,
                                const float* __restrict__ alph,
                                const int*   __restrict__ pointer,
                                float* __restrict__ out,
                                int V4, int Vext4, int chunk4,
                                int L_DEC, int L_SRC)
{
    extern __shared__ float srow[];            // chunk4*4 floats
    float4* s4 = reinterpret_cast<float4*>(srow);

    int row   = blockIdx.x / NCHUNK;           // b*L_DEC + t
    int chunk = blockIdx.x - row * NCHUNK;
    int b     = row / L_DEC;
    int t     = row - b * L_DEC;

    int lo = chunk * (chunk4 * 4);             // vocab range [lo, hi) for this CTA
    int hi = lo + chunk4 * 4;

    float pg    = __ldg(&p_gen[row]);
    float one_m = 1.0f - pg;

    // Phase 1: zero the shared accumulator chunk.
    float4 z = make_float4(0.f, 0.f, 0.f, 0.f);
    for (int i = threadIdx.x; i < chunk4; i += blockDim.x)
        s4[i] = z;
    __syncthreads();

    // Phase 2: scan the row's L_SRC (pointer, alpha) pairs; scatter the ones
    // that land in this chunk. Warp-contiguous segments: lanes of a warp
    // read consecutive s, so hit-loads of alpha touch consecutive L2 sectors.
    {
        const float* arow = alph + ((size_t)b * L_SRC) * L_DEC + t;
        const int*   prow = pointer + b * L_SRC;
        int lane  = threadIdx.x & 31;
        int warp  = threadIdx.x >> 5;
        int nwarp = blockDim.x >> 5;
        for (int s0 = warp * 32; s0 < L_SRC; s0 += nwarp * 32) {
            int s = s0 + lane;
            if (s < L_SRC) {
                int p = __ldg(&prow[s]);
                if (p >= lo && p < hi) {
                    float a = __ldg(&arow[(size_t)s * L_DEC]);
                    atomicAdd(&srow[p - lo], one_m * a);
                }
            }
        }
    }
    __syncthreads();

    // Phase 3: fused stream of this chunk: out = pg*dist (+ pad zeros) + copyp.
    {
        int base4 = chunk * chunk4;            // float4 offset within the row
        const float4* src = reinterpret_cast<const float4*>(dist) + (size_t)row * V4;
        float4*       dst = reinterpret_cast<float4*>(out) + (size_t)row * Vext4 + base4;
        for (int i = threadIdx.x; i < chunk4; i += blockDim.x) {
            float4 c = s4[i];
            int g = base4 + i;
            if (g < V4) {
                float4 d = __ldg(&src[g]);
                c.x = fmaf(pg, d.x, c.x);
                c.y = fmaf(pg, d.y, c.y);
                c.z = fmaf(pg, d.z, c.z);
                c.w = fmaf(pg, d.w, c.w);
            }
            dst[i] = c;
        }
    }
}

// Fallback: full-row-in-smem fused kernel (scalar), for shapes where the
// chunked/vectorized path doesn't divide evenly.
__global__ void copynet_fused_scalar_kernel(const float* __restrict__ dist,
                                            const float* __restrict__ p_gen,
                                            const float* __restrict__ alph,
                                            const int*   __restrict__ pointer,
                                            float* __restrict__ out,
                                            int V, int Vext,
                                            int L_DEC, int L_SRC)
{
    extern __shared__ float srow[];
    int row = blockIdx.x;
    int b   = row / L_DEC;
    int t   = row - b * L_DEC;
    float pg = __ldg(&p_gen[row]);
    float one_m = 1.0f - pg;

    for (int i = threadIdx.x; i < Vext; i += blockDim.x)
        srow[i] = 0.f;
    __syncthreads();

    const float* arow = alph + ((size_t)b * L_SRC) * L_DEC + t;
    const int*   prow = pointer + b * L_SRC;
    for (int s = threadIdx.x; s < L_SRC; s += blockDim.x)
        atomicAdd(&srow[__ldg(&prow[s])], one_m * __ldg(&arow[(size_t)s * L_DEC]));
    __syncthreads();

    for (int i = threadIdx.x; i < Vext; i += blockDim.x) {
        float c = srow[i];
        if (i < V) c = fmaf(pg, __ldg(&dist[(size_t)row * V + i]), c);
        out[(size_t)row * Vext + i] = c;
    }
}

extern "C" void kernel_launch(void* const* d_in, const int* in_sizes, int n_in,
                              void* d_out, int out_size)
{
    // metadata order: dist_t, p_gen, alph_t, batch_vocab, pointer
    const float* dist    = (const float*)d_in[0];
    const float* p_gen   = (const float*)d_in[1];
    const float* alph    = (const float*)d_in[2];
    const int*   pointer = (const int*)d_in[4];
    float*       out     = (float*)d_out;

    int BT    = in_sizes[1];                 // B * L_DEC   (2048)
    int Vext  = in_sizes[3];                 // 32128
    int BS    = in_sizes[4];                 // B * L_SRC   (4096)
    int L_DEC = in_sizes[2] / BS;            // 256
    int B     = BT / L_DEC;                  // 8
    int L_SRC = BS / B;                      // 512
    int V     = in_sizes[0] / BT;            // 32000

    bool vec_ok = (V % 4 == 0) && (Vext % (4 * NCHUNK) == 0);

    if (vec_ok) {
        int V4     = V / 4;
        int Vext4  = Vext / 4;
        int chunk4 = Vext4 / NCHUNK;          // 1004 float4 = 16.06 KB
        size_t smem_bytes = (size_t)chunk4 * 4 * sizeof(float);
        cudaFuncSetAttribute(copynet_fused_chunk_kernel,
                             cudaFuncAttributeMaxDynamicSharedMemorySize,
                             (int)smem_bytes);
        copynet_fused_chunk_kernel<<<BT * NCHUNK, 256, smem_bytes>>>(
            dist, p_gen, alph, pointer, out, V4, Vext4, chunk4, L_DEC, L_SRC);
    } else {
        size_t smem_bytes = (size_t)Vext * sizeof(float);
        cudaFuncSetAttribute(copynet_fused_scalar_kernel,
                             cudaFuncAttributeMaxDynamicSharedMemorySize,
                             (int)smem_bytes);
        copynet_fused_scalar_kernel<<<BT, 1024, smem_bytes>>>(
            dist, p_gen, alph, pointer, out, V, Vext, L_DEC, L_SRC);
    }
}